// round 14
// baseline (speedup 1.0000x reference)
#include <cuda_runtime.h>
#include <cuda_bf16.h>
#include <math.h>
#include <stdint.h>

#define N_TOK 8192
#define E_NUM 16
#define TOPK 2
#define DIN 1024
#define DHID 4096
#define DOUT 1024
#define NP (N_TOK * TOPK)
#define MAXT 160

#define OUT_GL ((size_t)N_TOK * DOUT)
#define OUT_IDX (OUT_GL + (size_t)N_TOK * E_NUM)
#define OUT_TOTAL (OUT_IDX + (size_t)N_TOK * TOPK)

// ---- GEMM tiling ----
#define BM 128
#define BN 128
#define BK 16
#define PADK 24                 // 48B row stride -> ldmatrix conflict-free
#define ROWB (PADK * 2)
#define ARRB (BM * ROWB)        // 6144 B per array
#define STGB (4 * ARRB)         // 24576 B per stage
#define NSTG 4
#define DYNSM (NSTG * STGB)     // 98304 B dynamic smem

// -------- device scratch (referenced ONLY inside kernels; NEVER passed as args) --------
__device__ __align__(256) __nv_bfloat16 g_xhi[(size_t)N_TOK * DIN];
__device__ __align__(256) __nv_bfloat16 g_xlo[(size_t)N_TOK * DIN];
__device__ __align__(256) __nv_bfloat16 g_hhi[((size_t)NP + BM) * DHID];
__device__ __align__(256) __nv_bfloat16 g_hlo[((size_t)NP + BM) * DHID];
__device__ __align__(256) __nv_bfloat16 g_w1hi[(size_t)E_NUM * DHID * DIN]; // [e][n][k]
__device__ __align__(256) __nv_bfloat16 g_w1lo[(size_t)E_NUM * DHID * DIN];
__device__ __align__(256) __nv_bfloat16 g_w2hi[(size_t)E_NUM * DOUT * DHID];
__device__ __align__(256) __nv_bfloat16 g_w2lo[(size_t)E_NUM * DOUT * DHID];
__device__ int   g_sorted[NP];
__device__ int   g_eid[NP];
__device__ float g_wt[NP];
__device__ int   g_cnt[E_NUM];
__device__ int   g_off[E_NUM + 1];
__device__ int   g_tile_e[MAXT];
__device__ int   g_tile_r[MAXT];
__device__ int   g_ntiles;

// ================= helpers =================
__device__ __forceinline__ uint32_t smem_u32(const void* p) {
    uint32_t a;
    asm("{ .reg .u64 t; cvta.to.shared.u64 t, %1; cvt.u32.u64 %0, t; }"
        : "=r"(a) : "l"(p));
    return a;
}
__device__ __forceinline__ void cpa16(uint32_t dst, const void* src) {
    asm volatile("cp.async.cg.shared.global [%0], [%1], 16;"
                 :: "r"(dst), "l"(src) : "memory");
}
#define CP_COMMIT() asm volatile("cp.async.commit_group;" ::: "memory")
#define CP_WAIT2()  asm volatile("cp.async.wait_group 2;" ::: "memory")

__device__ __forceinline__ void ldsm_x4(uint32_t* r, uint32_t addr) {
    asm volatile("ldmatrix.sync.aligned.m8n8.x4.shared.b16 {%0,%1,%2,%3}, [%4];"
        : "=r"(r[0]), "=r"(r[1]), "=r"(r[2]), "=r"(r[3]) : "r"(addr));
}
__device__ __forceinline__ void mma_bf16(float* c, const uint32_t* a,
                                         uint32_t b0, uint32_t b1) {
    asm volatile(
        "mma.sync.aligned.m16n8k16.row.col.f32.bf16.bf16.f32 "
        "{%0,%1,%2,%3}, {%4,%5,%6,%7}, {%8,%9}, {%0,%1,%2,%3};"
        : "+f"(c[0]), "+f"(c[1]), "+f"(c[2]), "+f"(c[3])
        : "r"(a[0]), "r"(a[1]), "r"(a[2]), "r"(a[3]), "r"(b0), "r"(b1));
}
__device__ __forceinline__ uint32_t packbf2(float a, float b) {
    __nv_bfloat162 t = __floats2bfloat162_rn(a, b);
    return *reinterpret_cast<uint32_t*>(&t);
}
__device__ __forceinline__ float bf16rt(float v) {
    return __bfloat162float(__float2bfloat16(v));
}

// ========== fused prep: gating | zero-out | xsplit | wsplit(W1) | wsplit(W2) ==========
#define PZ_GATE 512
#define PZ_ZERO 8192
#define PZ_XSP  8192
#define PZ_W1   65536
#define PZ_W2   65536
#define PZ_TOTAL (PZ_GATE + PZ_ZERO + PZ_XSP + PZ_W1 + PZ_W2)

__global__ void k_prep(const float* __restrict__ x,
                       const float* __restrict__ W1,
                       const float* __restrict__ W2,
                       const float* __restrict__ Wg,
                       const float* __restrict__ bg,
                       const float* __restrict__ bias,
                       float* __restrict__ out,
                       int write_extra) {
    __shared__ float sx[16][256];     // gating zone
    __shared__ float slog[16][16];
    __shared__ float sbias[16];
    __shared__ float s[32][33];       // wsplit zone

    int b = blockIdx.x;
    int tid = threadIdx.x;

    // ---- zone 0: gating (first so routing-critical work finishes earliest) ----
    if (b < PZ_GATE) {
        int tl = tid >> 4;
        int e  = tid & 15;
        int tok0 = b * 16;
        int token = tok0 + tl;

        if (tid < E_NUM) sbias[tid] = bias[tid];

        float acc = 0.f;
        for (int k0 = 0; k0 < DIN; k0 += 256) {
            __syncthreads();
            #pragma unroll
            for (int i = 0; i < 4; i++) {
                int lin4 = i * 1024 + tid * 4;
                int row = lin4 >> 8;
                int col = lin4 & 255;
                *(float4*)&sx[row][col] =
                    *(const float4*)(x + (size_t)(tok0 + row) * DIN + k0 + col);
            }
            __syncthreads();
            #pragma unroll 8
            for (int k = 0; k < 256; k++)
                acc += sx[tl][k] * Wg[(size_t)(k0 + k) * E_NUM + e];
        }
        acc += bg[e];

        if (write_extra)
            out[OUT_GL + (size_t)token * E_NUM + e] = acc;
        slog[tl][e] = acc;
        __syncthreads();

        if (e == 0) {
            float b0 = -INFINITY; int i0 = 0;
            #pragma unroll
            for (int j = 0; j < E_NUM; j++) {
                float v = slog[tl][j] + sbias[j];
                if (v > b0) { b0 = v; i0 = j; }
            }
            float b1v = -INFINITY; int i1 = 0;
            #pragma unroll
            for (int j = 0; j < E_NUM; j++) {
                if (j == i0) continue;
                float v = slog[tl][j] + sbias[j];
                if (v > b1v) { b1v = v; i1 = j; }
            }
            float l0 = slog[tl][i0], l1 = slog[tl][i1];
            float m = fmaxf(l0, l1);
            float e0 = expf(l0 - m), e1 = expf(l1 - m);
            float inv = 1.f / (e0 + e1);

            int p0 = token * 2, p1 = token * 2 + 1;
            g_eid[p0] = i0; g_wt[p0] = e0 * inv;
            g_eid[p1] = i1; g_wt[p1] = e1 * inv;
            if (write_extra) {
                out[OUT_IDX + p0] = (float)i0;
                out[OUT_IDX + p1] = (float)i1;
            }
        }
        return;
    }
    b -= PZ_GATE;

    if (b < PZ_ZERO) {
        size_t i = (size_t)b * 256 + tid;
        ((float4*)out)[i] = make_float4(0.f, 0.f, 0.f, 0.f);
        return;
    }
    b -= PZ_ZERO;
    if (b < PZ_XSP) {
        size_t i = ((size_t)b * 256 + tid) * 4;
        float4 f = *(const float4*)(x + i);
        float hx = bf16rt(f.x), hy = bf16rt(f.y), hz = bf16rt(f.z), hw = bf16rt(f.w);
        *(uint2*)(g_xhi + i) = make_uint2(packbf2(hx, hy), packbf2(hz, hw));
        *(uint2*)(g_xlo + i) = make_uint2(packbf2(f.x - hx, f.y - hy),
                                          packbf2(f.z - hz, f.w - hw));
        return;
    }
    b -= PZ_XSP;

    const float* W; int K, Nn, bx, by, e; bool w1;
    if (b < PZ_W1) {
        w1 = true;  W = W1; K = DIN;  Nn = DHID;
        bx = b & 127; by = (b >> 7) & 31; e = b >> 12;
    } else {
        b -= PZ_W1;
        w1 = false; W = W2; K = DHID; Nn = DOUT;
        bx = b & 31; by = (b >> 5) & 127; e = b >> 12;
    }
    int k0 = by * 32, n0 = bx * 32;
    int tx = tid & 31, ty = tid >> 5;   // 32 x 8
    const float* Wp = W + (size_t)e * K * Nn;
    #pragma unroll
    for (int i = 0; i < 4; i++)
        s[ty + 8 * i][tx] = Wp[(size_t)(k0 + ty + 8 * i) * Nn + n0 + tx];
    __syncthreads();
    #pragma unroll
    for (int i = 0; i < 4; i++) {
        int n = n0 + ty + 8 * i;
        float v = s[tx][ty + 8 * i];
        float h = bf16rt(v);
        size_t o = ((size_t)e * Nn + n) * K + k0 + tx;
        if (w1) { g_w1hi[o] = __float2bfloat16(h); g_w1lo[o] = __float2bfloat16(v - h); }
        else    { g_w2hi[o] = __float2bfloat16(h); g_w2lo[o] = __float2bfloat16(v - h); }
    }
}

// ================= fused route (1 block) =================
__global__ void k_route() {
    __shared__ int scnt[E_NUM], scur[E_NUM], soff[E_NUM + 1];
    int tid = threadIdx.x;
    if (tid < E_NUM) scnt[tid] = 0;
    __syncthreads();
    for (int p = tid; p < NP; p += 256)
        atomicAdd(&scnt[g_eid[p]], 1);
    __syncthreads();
    if (tid == 0) {
        int off = 0;
        soff[0] = 0; g_off[0] = 0;
        for (int e = 0; e < E_NUM; e++) {
            g_cnt[e] = scnt[e];
            off += scnt[e];
            soff[e + 1] = off; g_off[e + 1] = off;
        }
        int nt = 0;
        for (int e = 0; e < E_NUM; e++)
            for (int r = 0; r < scnt[e]; r += BM)
                if (nt < MAXT) { g_tile_e[nt] = e; g_tile_r[nt] = r; nt++; }
        g_ntiles = nt;
    }
    __syncthreads();
    if (tid < E_NUM) scur[tid] = soff[tid];
    __syncthreads();
    for (int p = tid; p < NP; p += 256) {
        int e = g_eid[p];
        int pos = atomicAdd(&scur[e], 1);
        g_sorted[pos] = p;
    }
}

// ===== grouped GEMM: 4-stage cp.async, fill-before-compute, 1 barrier/iter =====
template <int KTOT, int NTOT, bool G2>
__global__ void __launch_bounds__(256, 2)
k_mma_gemm(const float* __restrict__ bvec, float* __restrict__ outp) {
    int tm = blockIdx.y;
    if (tm >= g_ntiles) return;

    extern __shared__ __nv_bfloat16 dsm[];
    uint32_t smb = smem_u32(dsm);
    __shared__ float s_bias[BN];

    int tid = threadIdx.x, lane = tid & 31, w = tid >> 5;
    int warp_m = w & 3, warp_n = w >> 2;

    int e = g_tile_e[tm], r0 = g_tile_r[tm];
    int base = g_off[e], cnt = g_cnt[e];
    int gbase = base + r0;
    int n0g = blockIdx.x * BN;

    if (tid < BN) s_bias[tid] = bvec[(size_t)e * NTOT + n0g + tid];

    // ---- staging ----
    int row = tid >> 1, oct = tid & 1;
    const __nv_bfloat16* Ahi = G2 ? g_hhi : g_xhi;
    const __nv_bfloat16* Alo = G2 ? g_hlo : g_xlo;
    const __nv_bfloat16* Bhi = G2 ? g_w2hi : g_w1hi;
    const __nv_bfloat16* Blo = G2 ? g_w2lo : g_w1lo;

    size_t abase;
    if (G2) {
        abase = (size_t)(gbase + row) * KTOT;
    } else {
        int lr = r0 + row;
        int p = (lr < cnt) ? g_sorted[base + lr] : -1;
        abase = (size_t)((p >= 0) ? (p >> 1) : 0) * KTOT;
    }
    size_t bbase = ((size_t)e * NTOT + n0g + row) * KTOT;
    uint32_t dstoff = (uint32_t)(row * ROWB + oct * 16);

    auto fill = [&](int s, int it) {
        uint32_t sb = smb + s * STGB;
        size_t ko = (size_t)it * BK + oct * 8;
        cpa16(sb + 0 * ARRB + dstoff, Ahi + abase + ko);
        cpa16(sb + 1 * ARRB + dstoff, Alo + abase + ko);
        cpa16(sb + 2 * ARRB + dstoff, Bhi + bbase + ko);
        cpa16(sb + 3 * ARRB + dstoff, Blo + bbase + ko);
    };

    float acc[2][8][4] = {};
    const int NC = KTOT / BK;

    fill(0, 0); CP_COMMIT();
    fill(1, 1); CP_COMMIT();
    fill(2, 2); CP_COMMIT();

    // ldmatrix lane-relative offsets
    int lq = lane >> 3, lr8 = lane & 7;
    uint32_t arel = (uint32_t)((lr8 + (lq & 1) * 8) * ROWB + (lq >> 1) * 16);
    uint32_t brel = (uint32_t)((lr8 + (lq >> 1) * 8) * ROWB + (lq & 1) * 16);
    int t4 = lane >> 2;

    for (int it = 0; it < NC; it++) {
        int s = it & 3;
        CP_WAIT2();
        __syncthreads();

        // fill first: stage (it+3)&3 == (it-1)&3 was fully consumed before the
        // barrier above, so it is free; issuing loads here gives them the whole
        // MMA block below as latency cover.
        if (it + 3 < NC) fill((it + 3) & 3, it + 3);
        CP_COMMIT();

        uint32_t sb = smb + s * STGB;
        uint32_t ah[2][4], al[2][4];
        #pragma unroll
        for (int i = 0; i < 2; i++) {
            uint32_t ra = sb + (uint32_t)((warp_m * 32 + i * 16) * ROWB) + arel;
            ldsm_x4(ah[i], ra);
            ldsm_x4(al[i], ra + ARRB);
        }
        #pragma unroll
        for (int jp = 0; jp < 4; jp++) {
            uint32_t rb = sb + 2 * ARRB +
                (uint32_t)((warp_n * 64 + jp * 16) * ROWB) + brel;
            uint32_t bh[4], bl[4];
            ldsm_x4(bh, rb);
            ldsm_x4(bl, rb + ARRB);
            #pragma unroll
            for (int j2 = 0; j2 < 2; j2++) {
                int jn = jp * 2 + j2;
                #pragma unroll
                for (int i = 0; i < 2; i++) {
                    mma_bf16(acc[i][jn], ah[i], bh[2 * j2], bh[2 * j2 + 1]);
                    mma_bf16(acc[i][jn], ah[i], bl[2 * j2], bl[2 * j2 + 1]);
                    mma_bf16(acc[i][jn], al[i], bh[2 * j2], bh[2 * j2 + 1]);
                }
            }
        }
    }

    // ---- epilogue ----
    #pragma unroll
    for (int i = 0; i < 2; i++) {
        #pragma unroll
        for (int jn = 0; jn < 8; jn++) {
            int colb = warp_n * 64 + jn * 8 + (lane & 3) * 2;
            float bb0 = s_bias[colb], bb1 = s_bias[colb + 1];
            #pragma unroll
            for (int rp = 0; rp < 2; rp++) {
                int orow = warp_m * 32 + i * 16 + t4 + 8 * rp;
                int lr = r0 + orow;
                if (lr >= cnt) continue;
                int pair = g_sorted[base + lr];
                float v0 = acc[i][jn][2 * rp]     + bb0;
                float v1 = acc[i][jn][2 * rp + 1] + bb1;
                if (!G2) {
                    v0 = fmaxf(v0, 0.f);
                    v1 = fmaxf(v1, 0.f);
                    float h0 = bf16rt(v0), h1 = bf16rt(v1);
                    size_t o = (size_t)(gbase + orow) * DHID + n0g + colb;
                    *(uint32_t*)&g_hhi[o] = packbf2(h0, h1);
                    *(uint32_t*)&g_hlo[o] = packbf2(v0 - h0, v1 - h1);
                } else {
                    int token = pair >> 1;
                    float wgt = g_wt[pair];
                    float* op = outp + (size_t)token * DOUT + n0g + colb;
                    atomicAdd(op,     wgt * v0);
                    atomicAdd(op + 1, wgt * v1);
                }
            }
        }
    }
}

// ================= launch =================
extern "C" void kernel_launch(void* const* d_in, const int* in_sizes, int n_in,
                              void* d_out, int out_size) {
    const float* x    = (const float*)d_in[0];
    const float* Wg   = (const float*)d_in[1];
    const float* bg   = (const float*)d_in[2];
    const float* W1   = (const float*)d_in[3];
    const float* b1   = (const float*)d_in[4];
    const float* W2   = (const float*)d_in[5];
    const float* b2   = (const float*)d_in[6];
    const float* bias = (const float*)d_in[7];
    float* out = (float*)d_out;

    int write_extra = ((size_t)out_size >= OUT_TOTAL) ? 1 : 0;

    cudaFuncSetAttribute(k_mma_gemm<DIN, DHID, false>,
                         cudaFuncAttributeMaxDynamicSharedMemorySize, DYNSM);
    cudaFuncSetAttribute(k_mma_gemm<DHID, DOUT, true>,
                         cudaFuncAttributeMaxDynamicSharedMemorySize, DYNSM);

    k_prep<<<PZ_TOTAL, 256>>>(x, W1, W2, Wg, bg, bias, out, write_extra);
    k_route<<<1, 256>>>();
    k_mma_gemm<DIN, DHID, false><<<dim3(DHID / BN, MAXT), 256, DYNSM>>>(b1, nullptr);
    k_mma_gemm<DHID, DOUT, true><<<dim3(DOUT / BN, MAXT), 256, DYNSM>>>(b2, out);
}